// round 5
// baseline (speedup 1.0000x reference)
#include <cuda_runtime.h>

#define TT   128   // timesteps
#define NN   32    // nodes
#define EE   512   // edges per timestep
#define INC  64    // input channels
#define HH   128   // hidden
#define SL   16    // seq len (steps per window)
#define WB   8     // windows per block
#define G4   512   // 4*HH gates
#define HROW 36    // padded row stride in floats (144B, 16B-aligned)

// ---------------- device scratch (static, no allocs) ----------------
__device__ float g_hgcn  [TT * NN * HH];   // [t][n][h]
__device__ float g_P1    [NN * TT * G4];   // [n][t][j][4]  (gate-interleaved)
__device__ float g_WihTI1[NN * HH * G4];   // [n][k][j][4]
__device__ float g_WhhTI1[NN * HH * G4];
__device__ float g_WihTI2[NN * HH * G4];
__device__ float g_WhhTI2[NN * HH * G4];
__device__ float g_WfcT  [NN * HH * HH];   // [n][k][r]

// ---------------- helpers ----------------
__device__ __forceinline__ float sigf(float x) {
    return __fdividef(1.0f, 1.0f + __expf(-x));
}
__device__ __forceinline__ float tanhfast(float x) {
    x = fminf(fmaxf(x, -15.0f), 15.0f);
    float e = __expf(2.0f * x);
    return __fdividef(e - 1.0f, e + 1.0f);
}
__device__ __forceinline__ unsigned long long pk2(float a, float b) {
    unsigned long long r;
    asm("mov.b64 %0,{%1,%2};" : "=l"(r) : "f"(a), "f"(b));
    return r;
}
__device__ __forceinline__ void upk2(unsigned long long v, float& a, float& b) {
    asm("mov.b64 {%0,%1},%2;" : "=f"(a), "=f"(b) : "l"(v));
}
__device__ __forceinline__ void fma2(unsigned long long& d, unsigned long long a, unsigned long long b) {
    asm("fma.rn.f32x2 %0,%1,%2,%0;" : "+l"(d) : "l"(a), "l"(b));
}

// ---------------- tiled transpose + gate-interleave for all 4 LSTM weights ----
// out[n][k][j*4+g] = in[n][g*128+j][k]
__global__ void __launch_bounds__(256) tik4_kernel(
    const float* __restrict__ Wih1, const float* __restrict__ Whh1,
    const float* __restrict__ Wih2, const float* __restrict__ Whh2)
{
    __shared__ float st[4][32][33];
    int n  = blockIdx.x;
    int jt = (blockIdx.y >> 2) * 32;
    int kt = (blockIdx.y & 3) * 32;
    int m  = blockIdx.z;
    const float* srcs[4] = {Wih1, Whh1, Wih2, Whh2};
    float* dsts[4] = {g_WihTI1, g_WhhTI1, g_WihTI2, g_WhhTI2};
    const float* src = srcs[m] + (size_t)n * G4 * HH;
    float4* dst = (float4*)(dsts[m] + (size_t)n * HH * G4);
    int tx = threadIdx.x, ty = threadIdx.y;

    #pragma unroll
    for (int g = 0; g < 4; g++)
        for (int jj = ty; jj < 32; jj += 8)
            st[g][jj][tx] = src[(g * HH + jt + jj) * HH + kt + tx];
    __syncthreads();
    for (int kk = ty; kk < 32; kk += 8) {
        float4 v;
        v.x = st[0][tx][kk]; v.y = st[1][tx][kk];
        v.z = st[2][tx][kk]; v.w = st[3][tx][kk];
        dst[(kt + kk) * HH + jt + tx] = v;
    }
}

// ---------------- plain transpose for Wfc: out[n][k][r] = in[n][r][k] ----------------
__global__ void fct_kernel(const float* __restrict__ in, float* __restrict__ out) {
    int n = blockIdx.x;
    const float* src = in + (size_t)n * HH * HH;
    float* dst = out + (size_t)n * HH * HH;
    for (int i = threadIdx.x; i < HH * HH; i += blockDim.x) {
        int k = i >> 7, r = i & 127;
        dst[k * HH + r] = src[r * HH + k];
    }
}

// ---------------- 2-layer GCN per timestep, dense-adjacency formulation ----------------
__global__ void __launch_bounds__(256) gcn_kernel(
    const float* __restrict__ x, const int* __restrict__ ei,
    const float* __restrict__ W1, const float* __restrict__ b1,
    const float* __restrict__ W2, const float* __restrict__ b2)
{
    int t = blockIdx.x, tid = threadIdx.x;
    __shared__ float A[NN * HH];
    __shared__ float B[NN * HH];
    __shared__ float Adj[NN * NN];
    __shared__ float dinv[NN];
    __shared__ int   deg[NN];
    __shared__ int   rowS[EE];
    __shared__ int   colS[EE];

    const int* rowp = ei + (size_t)t * 2 * EE;
    const int* colp = rowp + EE;

    if (tid < NN) deg[tid] = 1;                    // self-loop
    for (int i = tid; i < NN * NN; i += 256) Adj[i] = 0.0f;
    __syncthreads();
    for (int e = tid; e < EE; e += 256) {
        int r = rowp[e], c = colp[e];
        rowS[e] = r; colS[e] = c;
        atomicAdd(&deg[c], 1);
    }
    __syncthreads();
    if (tid < NN) dinv[tid] = rsqrtf((float)deg[tid]);
    __syncthreads();
    for (int e = tid; e < EE; e += 256) {
        int r = rowS[e], c = colS[e];
        atomicAdd(&Adj[c * NN + r], dinv[r] * dinv[c]);
    }
    if (tid < NN) atomicAdd(&Adj[tid * NN + tid], dinv[tid] * dinv[tid]);
    __syncthreads();

    // layer 1: A = x_t @ W1
    const float* xt = x + (size_t)t * NN * INC;
    for (int o = tid; o < NN * HH; o += 256) {
        int r = o >> 7, c = o & 127;
        float s = 0.0f;
        #pragma unroll 8
        for (int k = 0; k < INC; k++) s += xt[r * INC + k] * W1[k * HH + c];
        A[o] = s;
    }
    __syncthreads();
    // B = relu(Adj @ A + b1)
    for (int o = tid; o < NN * HH; o += 256) {
        int cn = o >> 7, ch = o & 127;
        float s = 0.0f;
        #pragma unroll
        for (int r = 0; r < NN; r++) s += Adj[cn * NN + r] * A[r * HH + ch];
        B[o] = fmaxf(s + b1[ch], 0.0f);
    }
    __syncthreads();
    // layer 2: A = B @ W2
    for (int o = tid; o < NN * HH; o += 256) {
        int r = o >> 7, c = o & 127;
        float s = 0.0f;
        #pragma unroll 8
        for (int k = 0; k < HH; k++) s += B[r * HH + k] * W2[k * HH + c];
        A[o] = s;
    }
    __syncthreads();
    // out = relu(Adj @ A + b2) -> global
    for (int o = tid; o < NN * HH; o += 256) {
        int cn = o >> 7, ch = o & 127;
        float s = 0.0f;
        #pragma unroll
        for (int r = 0; r < NN; r++) s += Adj[cn * NN + r] * A[r * HH + ch];
        g_hgcn[((size_t)t * NN + cn) * HH + ch] = fmaxf(s + b2[ch], 0.0f);
    }
}

// ---------------- precompute P1[n][t][j][4] = Wih1[n] @ h_gcn[t][n] ----------------
// grid (NN, 16): 8 timesteps per block; 256 threads = (j in 0..127, th in 0..1)
__global__ void __launch_bounds__(256) p1_kernel() {
    int n = blockIdx.x, tb = blockIdx.y * 8;
    __shared__ float hs[8][HH];
    int tid = threadIdx.x;
    for (int i = tid; i < 8 * HH; i += 256) {
        int tt = i >> 7, k = i & 127;
        hs[tt][k] = g_hgcn[((size_t)(tb + tt) * NN + n) * HH + k];
    }
    __syncthreads();
    int j = tid & 127, th = tid >> 7;
    const float4* Wp = (const float4*)(g_WihTI1 + (size_t)n * HH * G4);
    float4 acc[4];
    #pragma unroll
    for (int i = 0; i < 4; i++) acc[i] = make_float4(0.f, 0.f, 0.f, 0.f);
    #pragma unroll 4
    for (int k = 0; k < HH; k++) {
        float4 wv = Wp[k * HH + j];
        #pragma unroll
        for (int i = 0; i < 4; i++) {
            float hv = hs[th * 4 + i][k];
            acc[i].x += wv.x * hv; acc[i].y += wv.y * hv;
            acc[i].z += wv.z * hv; acc[i].w += wv.w * hv;
        }
    }
    float4* out = (float4*)(g_P1 + (size_t)n * TT * G4);
    #pragma unroll
    for (int i = 0; i < 4; i++) out[(tb + th * 4 + i) * HH + j] = acc[i];
}

// ---------------- main 2-layer windowed LSTM + fc + heads ----------------
// block = (node n, chunk of 8 windows), 128 threads: thread j owns hidden channel j.
// Gate-pair f32x2 packing: acc_if = (i,f) preact, acc_go = (g,o) preact.
// Row layout hd[buf][k][4w..4w+3] = (h1,h1,h2,h2); h2 carried in registers between steps.
__global__ void __launch_bounds__(128, 3) lstm_kernel(
    const float* __restrict__ bih1, const float* __restrict__ bhh1,
    const float* __restrict__ bih2, const float* __restrict__ bhh2,
    const float* __restrict__ bfc,
    const float* __restrict__ Wout0, const float* __restrict__ bout0,
    const float* __restrict__ Wout1, const float* __restrict__ bout1,
    float* __restrict__ dout)
{
    int n = blockIdx.x, chunk = blockIdx.y;
    int j = threadIdx.x;
    int tbase = chunk * WB;

    __shared__ __align__(16) float hd[2][HH][HROW];

    float c1[WB], c2[WB], h2reg[WB];
    #pragma unroll
    for (int w = 0; w < WB; w++) { c1[w] = 0.f; c2[w] = 0.f; h2reg[w] = 0.f; }

    // zero buffer 0 rows (h1 part read at s=0; h2 part read at s=0 layer2 via combined slot
    // written at s=0 layer1 from h2reg=0, so only buf0 h1 part strictly needed — zero all 4)
    #pragma unroll
    for (int w = 0; w < WB; w++) {
        float4 z = make_float4(0.f, 0.f, 0.f, 0.f);
        *(float4*)(&hd[0][j][4 * w]) = z;
    }

    unsigned long long b1_if, b1_go, b2_if, b2_go;
    {
        float i1 = bih1[n * G4 + 0 * HH + j] + bhh1[n * G4 + 0 * HH + j];
        float f1 = bih1[n * G4 + 1 * HH + j] + bhh1[n * G4 + 1 * HH + j];
        float g1 = bih1[n * G4 + 2 * HH + j] + bhh1[n * G4 + 2 * HH + j];
        float o1 = bih1[n * G4 + 3 * HH + j] + bhh1[n * G4 + 3 * HH + j];
        float i2 = bih2[n * G4 + 0 * HH + j] + bhh2[n * G4 + 0 * HH + j];
        float f2 = bih2[n * G4 + 1 * HH + j] + bhh2[n * G4 + 1 * HH + j];
        float g2 = bih2[n * G4 + 2 * HH + j] + bhh2[n * G4 + 2 * HH + j];
        float o2 = bih2[n * G4 + 3 * HH + j] + bhh2[n * G4 + 3 * HH + j];
        b1_if = pk2(i1, f1); b1_go = pk2(g1, o1);
        b2_if = pk2(i2, f2); b2_go = pk2(g2, o2);
    }

    const float4* Wh1 = (const float4*)(g_WhhTI1 + (size_t)n * HH * G4);
    const float4* Wi2 = (const float4*)(g_WihTI2 + (size_t)n * HH * G4);
    const float4* Wh2 = (const float4*)(g_WhhTI2 + (size_t)n * HH * G4);
    const float4* P1p = (const float4*)(g_P1     + (size_t)n * TT * G4);
    __syncthreads();

    for (int s = 0; s < SL; s++) {
        int rb = s & 1, wbuf = rb ^ 1;

        // ---- layer 1 gates: b1 + P1[ts] + Whh1 @ h1 ----
        unsigned long long aif[WB], ago[WB];
        #pragma unroll
        for (int w = 0; w < WB; w++) { aif[w] = b1_if; ago[w] = b1_go; }

        #pragma unroll 4
        for (int k = 0; k < HH; k++) {
            float4 wv = Wh1[k * HH + j];
            unsigned long long w_if = pk2(wv.x, wv.y);
            unsigned long long w_go = pk2(wv.z, wv.w);
            const float* row = hd[rb][k];
            #pragma unroll
            for (int w = 0; w < WB; w++) {
                unsigned long long hdup = *(const unsigned long long*)(row + 4 * w);
                fma2(aif[w], w_if, hdup);
                fma2(ago[w], w_go, hdup);
            }
        }

        float h1n[WB];
        #pragma unroll
        for (int w = 0; w < WB; w++) {
            float iv, fv, gv, ov;
            upk2(aif[w], iv, fv);
            upk2(ago[w], gv, ov);
            int ts = tbase + w - (SL - 1) + s;
            if (ts >= 0) {
                float4 p = P1p[ts * HH + j];
                iv += p.x; fv += p.y; gv += p.z; ov += p.w;
            }
            c1[w] = sigf(fv) * c1[w] + sigf(iv) * tanhfast(gv);
            h1n[w] = sigf(ov) * tanhfast(c1[w]);
        }
        // write (h1new, h1new, h2old, h2old) — one STS.128 per window
        #pragma unroll
        for (int w = 0; w < WB; w++) {
            float4 v;
            v.x = h1n[w]; v.y = h1n[w]; v.z = h2reg[w]; v.w = h2reg[w];
            *(float4*)(&hd[wbuf][j][4 * w]) = v;
        }
        __syncthreads();

        // ---- layer 2 gates: b2 + Wih2 @ h1new + Whh2 @ h2old ----
        #pragma unroll
        for (int w = 0; w < WB; w++) { aif[w] = b2_if; ago[w] = b2_go; }

        #pragma unroll 2
        for (int k = 0; k < HH; k++) {
            float4 wiv = Wi2[k * HH + j];
            float4 whv = Wh2[k * HH + j];
            unsigned long long wi_if = pk2(wiv.x, wiv.y);
            unsigned long long wi_go = pk2(wiv.z, wiv.w);
            unsigned long long wh_if = pk2(whv.x, whv.y);
            unsigned long long wh_go = pk2(whv.z, whv.w);
            const float* row = hd[wbuf][k];
            #pragma unroll
            for (int w = 0; w < WB; w++) {
                // one LDS.128: (h1,h1,h2,h2)
                float4 hh = *(const float4*)(row + 4 * w);
                unsigned long long h1d, h2d;
                asm("mov.b64 %0,{%2,%3}; mov.b64 %1,{%4,%5};"
                    : "=l"(h1d), "=l"(h2d)
                    : "f"(hh.x), "f"(hh.y), "f"(hh.z), "f"(hh.w));
                fma2(aif[w], wi_if, h1d); fma2(aif[w], wh_if, h2d);
                fma2(ago[w], wi_go, h1d); fma2(ago[w], wh_go, h2d);
            }
        }

        #pragma unroll
        for (int w = 0; w < WB; w++) {
            float iv, fv, gv, ov;
            upk2(aif[w], iv, fv);
            upk2(ago[w], gv, ov);
            c2[w] = sigf(fv) * c2[w] + sigf(iv) * tanhfast(gv);
            h2reg[w] = sigf(ov) * tanhfast(c2[w]);
        }
        // no sync here: next step's layer-1 write targets the other buffer, and
        // all reads of that buffer happened before this step's sync.
    }

    __syncthreads();   // drain last layer-2 reads before reusing hd[0]

    // ---- last = relu(h2) -> hd[0] (dup), fc = Wfc @ last + bfc -> hd[1] ----
    #pragma unroll
    for (int w = 0; w < WB; w++) {
        float r = fmaxf(h2reg[w], 0.0f);
        *(unsigned long long*)(&hd[0][j][4 * w]) = pk2(r, r);
    }
    __syncthreads();

    {
        float fcv[WB];
        float bb = bfc[n * HH + j];
        #pragma unroll
        for (int w = 0; w < WB; w++) fcv[w] = bb;
        const float* Wf = g_WfcT + (size_t)n * HH * HH;
        #pragma unroll 4
        for (int k = 0; k < HH; k++) {
            float wf = Wf[k * HH + j];
            const float* row = hd[0][k];
            #pragma unroll
            for (int w = 0; w < WB; w++) fcv[w] += wf * row[4 * w];
        }
        __syncthreads();
        #pragma unroll
        for (int w = 0; w < WB; w++) hd[1][j][w] = fcv[w];
        __syncthreads();
    }

    // ---- heads: 8 windows x (4 + 2) outputs ----
    if (j < 48) {
        int w = j / 6, q = j % 6;
        const float* wr; float bo;
        if (q < 4) { wr = Wout0 + (size_t)(n * 4 + q) * HH;       bo = bout0[n * 4 + q]; }
        else       { wr = Wout1 + (size_t)(n * 2 + (q - 4)) * HH; bo = bout1[n * 2 + (q - 4)]; }
        float s2 = bo;
        #pragma unroll 8
        for (int k = 0; k < HH; k++) s2 += wr[k] * hd[1][k][w];
        int t = tbase + w;
        if (q < 4) dout[((size_t)t * NN + n) * 4 + q] = s2;
        else       dout[(size_t)TT * NN * 4 + ((size_t)t * NN + n) * 2 + (q - 4)] = s2;
    }
}

// ---------------- targets pass-through ----------------
__global__ void copy_y_kernel(const float* __restrict__ y, float* __restrict__ dst) {
    int i = blockIdx.x * 256 + threadIdx.x;
    if (i < TT * NN * 4) dst[i] = y[i];
}

// ---------------- launch ----------------
extern "C" void kernel_launch(void* const* d_in, const int* in_sizes, int n_in,
                              void* d_out, int out_size)
{
    const float* x     = (const float*)d_in[0];
    const int*   ei    = (const int*)  d_in[1];
    const float* y     = (const float*)d_in[3];
    const float* W1    = (const float*)d_in[4];
    const float* b1    = (const float*)d_in[5];
    const float* W2    = (const float*)d_in[6];
    const float* b2    = (const float*)d_in[7];
    const float* Wih1  = (const float*)d_in[8];
    const float* Whh1  = (const float*)d_in[9];
    const float* bih1  = (const float*)d_in[10];
    const float* bhh1  = (const float*)d_in[11];
    const float* Wih2  = (const float*)d_in[12];
    const float* Whh2  = (const float*)d_in[13];
    const float* bih2  = (const float*)d_in[14];
    const float* bhh2  = (const float*)d_in[15];
    const float* Wfc   = (const float*)d_in[16];
    const float* bfc   = (const float*)d_in[17];
    const float* Wout0 = (const float*)d_in[18];
    const float* bout0 = (const float*)d_in[19];
    const float* Wout1 = (const float*)d_in[20];
    const float* bout1 = (const float*)d_in[21];
    float* out = (float*)d_out;

    void* pWfcT;
    cudaGetSymbolAddress(&pWfcT, g_WfcT);

    tik4_kernel<<<dim3(NN, 16, 4), dim3(32, 8)>>>(Wih1, Whh1, Wih2, Whh2);
    fct_kernel<<<32, 256>>>(Wfc, (float*)pWfcT);

    gcn_kernel<<<TT, 256>>>(x, ei, W1, b1, W2, b2);
    p1_kernel<<<dim3(NN, 16), 256>>>();

    lstm_kernel<<<dim3(NN, TT / WB), HH>>>(bih1, bhh1, bih2, bhh2, bfc,
                                           Wout0, bout0, Wout1, bout1, out);

    copy_y_kernel<<<(TT * NN * 4 + 255) / 256, 256>>>(y, out + (size_t)TT * NN * 4 + (size_t)TT * NN * 2);
}